// round 1
// baseline (speedup 1.0000x reference)
#include <cuda_runtime.h>
#include <math.h>
#include <stdint.h>

#define NMAX 100000
#define F 128
#define HEADC 106   // 64 + 40 + 1 + 1

// ---------------- scratch (static device globals; no allocation allowed) ---
__device__ float g_h[(size_t)NMAX * F];       // GEMM output / scatter source
__device__ float g_agg[(size_t)NMAX * F];     // aggregation buffer
__device__ float g_head[(size_t)NMAX * HEADC];
__device__ float g_dinv[NMAX];
__device__ int   g_deg[NMAX];
__device__ float g_hw[F * HEADC];
__device__ float g_hb[HEADC];
__device__ int   g_is64;

// ---------------- dtype detection: int64 vs int32 edge_index ---------------
// Values are node ids < 100000 < 2^31, so under int64 every odd 32-bit word
// is 0. Under int32 odd words are edge endpoints (P[=0 for 256 samples] ~ 0).
__global__ void detect_kernel(const int* __restrict__ e) {
    int l = threadIdx.x;
    int bad = 0;
    for (int j = l; j < 256; j += 32)
        if (e[2 * j + 1] != 0) bad = 1;
    unsigned b = __ballot_sync(0xffffffffu, bad);
    if (l == 0) g_is64 = (b == 0) ? 1 : 0;
}

__device__ __forceinline__ int ldidx(const void* p, long long i, int is64) {
    return is64 ? (int)((const long long*)p)[i] : ((const int*)p)[i];
}

// ---------------- degree / normalization -----------------------------------
__global__ void zero_deg_kernel(int n) {
    int i = blockIdx.x * blockDim.x + threadIdx.x;
    if (i < n) g_deg[i] = 0;
}

__global__ void count_deg_kernel(const void* __restrict__ eidx, long long E) {
    long long e = (long long)blockIdx.x * blockDim.x + threadIdx.x;
    if (e >= E) return;
    int c = ldidx(eidx, E + e, g_is64);
    atomicAdd(&g_deg[c], 1);
}

__global__ void dinv_kernel(int n) {
    int i = blockIdx.x * blockDim.x + threadIdx.x;
    if (i < n) g_dinv[i] = rsqrtf((float)(g_deg[i] + 1));  // +1 self-loop
}

// ---------------- generic SGEMM: C[M,Nc] = A[M,128] @ W[128,Nc] (+bias) ----
// W fully staged in shared; 4 rows per warp to amortize shared W reads.
__global__ void gemm_kernel(const float* __restrict__ A,
                            const float* __restrict__ W,
                            const float* __restrict__ bias,
                            float* __restrict__ C, int M, int Nc) {
    extern __shared__ float sm[];
    int NcPad = (Nc + 3) & ~3;
    float* Ws = sm;                    // F * NcPad
    float* xs = Ws + F * NcPad;        // 8 warps * 4 rows * F
    float* sb = xs + 8 * 4 * F;        // NcPad

    int tid = threadIdx.x;
    for (int i = tid; i < F * NcPad; i += blockDim.x) {
        int c = i % NcPad;
        int k = i / NcPad;
        Ws[i] = (c < Nc) ? W[k * Nc + c] : 0.f;
    }
    for (int c = tid; c < NcPad; c += blockDim.x)
        sb[c] = (bias != nullptr && c < Nc) ? bias[c] : 0.f;
    __syncthreads();

    int wid = tid >> 5, l = tid & 31;
    long long row0 = ((long long)blockIdx.x * 8 + wid) * 4;
    if (row0 >= M) return;

    float* xw = xs + wid * 4 * F;
#pragma unroll
    for (int rr = 0; rr < 4; rr++) {
        long long r = row0 + rr;
        float4 v = make_float4(0.f, 0.f, 0.f, 0.f);
        if (r < M) v = __ldg((const float4*)(A + r * F) + l);
        *(float4*)&xw[rr * F + 4 * l] = v;
    }
    __syncwarp();

    float acc[4][4];
#pragma unroll
    for (int rr = 0; rr < 4; rr++)
#pragma unroll
        for (int m = 0; m < 4; m++) acc[rr][m] = 0.f;

    const float4* WsV = (const float4*)Ws;
    int ncp4 = NcPad >> 2;
#pragma unroll
    for (int k = 0; k < F; k += 4) {
        float4 w4[4], xr[4];
#pragma unroll
        for (int kk = 0; kk < 4; kk++) w4[kk] = WsV[(k + kk) * ncp4 + l];
#pragma unroll
        for (int rr = 0; rr < 4; rr++) xr[rr] = *(const float4*)&xw[rr * F + k];
#pragma unroll
        for (int rr = 0; rr < 4; rr++) {
            const float* xf = (const float*)&xr[rr];
#pragma unroll
            for (int kk = 0; kk < 4; kk++) {
                const float* wf = (const float*)&w4[kk];
                float xv = xf[kk];
                acc[rr][0] += xv * wf[0];
                acc[rr][1] += xv * wf[1];
                acc[rr][2] += xv * wf[2];
                acc[rr][3] += xv * wf[3];
            }
        }
    }

    int c0 = 4 * l;
#pragma unroll
    for (int rr = 0; rr < 4; rr++) {
        long long r = row0 + rr;
        if (r >= M) break;
#pragma unroll
        for (int m = 0; m < 4; m++) {
            int c = c0 + m;
            if (c < Nc) C[r * Nc + c] = acc[rr][m] + sb[c];
        }
    }
}

// ---------------- aggregation ----------------------------------------------
// init: agg[i,:] = h[i,:] * dinv[i]^2  (self-loop term)
__global__ void init_agg_kernel(int n) {
    long long t = (long long)blockIdx.x * blockDim.x + threadIdx.x;
    if (t >= (long long)n * 32) return;
    int node = (int)(t >> 5);
    float d = g_dinv[node];
    float d2 = d * d;
    float4 v = ((const float4*)g_h)[t];
    v.x *= d2; v.y *= d2; v.z *= d2; v.w *= d2;
    ((float4*)g_agg)[t] = v;
}

// scatter: one warp per edge; 512B gather + 32 x red.v4 (L2-resident)
__global__ void scatter_kernel(const void* __restrict__ eidx, long long E) {
    long long w = (long long)blockIdx.x * (blockDim.x >> 5) + (threadIdx.x >> 5);
    if (w >= E) return;
    int l = threadIdx.x & 31;
    int is64 = g_is64;
    int r = ldidx(eidx, w, is64);
    int c = ldidx(eidx, E + w, is64);
    float nrm = g_dinv[r] * g_dinv[c];
    float4 v = __ldg((const float4*)(g_h + (size_t)r * F) + l);
    v.x *= nrm; v.y *= nrm; v.z *= nrm; v.w *= nrm;
    float* dst = g_agg + (size_t)c * F + 4 * l;
    asm volatile("red.global.add.v4.f32 [%0], {%1,%2,%3,%4};"
                 :: "l"(dst), "f"(v.x), "f"(v.y), "f"(v.z), "f"(v.w)
                 : "memory");
}

// ---------------- epilogues -------------------------------------------------
__global__ void epi1_kernel(int n, const float* __restrict__ b1,
                            const float* __restrict__ gamma,
                            const float* __restrict__ beta,
                            const float* __restrict__ mean,
                            const float* __restrict__ var) {
    long long t = (long long)blockIdx.x * blockDim.x + threadIdx.x;
    if (t >= (long long)n * F) return;
    int j = (int)(t & (F - 1));
    float v = g_agg[t] + b1[j];
    float sc = gamma[j] * rsqrtf(var[j] + 1e-5f);
    v = (v - mean[j]) * sc + beta[j];
    g_agg[t] = fmaxf(v, 0.f);
}

__global__ void epi2_kernel(int n, const float* __restrict__ b2) {
    long long t = (long long)blockIdx.x * blockDim.x + threadIdx.x;
    if (t >= (long long)n * F) return;
    g_agg[t] += b2[t & (F - 1)];
}

// ---------------- head weight packing ---------------------------------------
__global__ void pack_heads_kernel(const float* __restrict__ cls_w,
                                  const float* __restrict__ cls_b,
                                  const float* __restrict__ sim_w,
                                  const float* __restrict__ sim_b,
                                  const float* __restrict__ hom_w,
                                  const float* __restrict__ hom_b,
                                  const float* __restrict__ ent_w,
                                  const float* __restrict__ ent_b) {
    int t = blockIdx.x * blockDim.x + threadIdx.x;
    if (t < F * HEADC) {
        int k = t / HEADC, c = t % HEADC;
        float v;
        if (c < 64)        v = cls_w[k * 64 + c];
        else if (c < 104)  v = sim_w[k * 40 + (c - 64)];
        else if (c == 104) v = hom_w[k];
        else               v = ent_w[k];
        g_hw[t] = v;
    }
    if (t < HEADC) {
        float v;
        if (t < 64)        v = cls_b[t];
        else if (t < 104)  v = sim_b[t - 64];
        else if (t == 104) v = hom_b[0];
        else               v = ent_b[0];
        g_hb[t] = v;
    }
}

// ---------------- finisher: softmaxes + sigmoids -> d_out --------------------
__global__ void finish_kernel(int n, float* __restrict__ out) {
    long long wg = (long long)blockIdx.x * (blockDim.x >> 5) + (threadIdx.x >> 5);
    if (wg >= n) return;
    int l = threadIdx.x & 31;
    const float* g = g_head + wg * HEADC;

    float* out_main = out;                               // [n,64]
    float* out_sim  = out + (size_t)n * 64;              // [n,40]
    float* out_hom  = out + (size_t)n * 104;             // [n]
    float* out_ent  = out + (size_t)n * 105;             // [n]

    // ---- log_softmax over cols [0,64)
    float a = g[l], b = g[32 + l];
    float m = fmaxf(a, b);
#pragma unroll
    for (int o = 16; o; o >>= 1) m = fmaxf(m, __shfl_xor_sync(0xffffffffu, m, o));
    float s = expf(a - m) + expf(b - m);
#pragma unroll
    for (int o = 16; o; o >>= 1) s += __shfl_xor_sync(0xffffffffu, s, o);
    float ls = m + logf(s);
    out_main[wg * 64 + l]      = a - ls;
    out_main[wg * 64 + 32 + l] = b - ls;

    // ---- softmax over cols [64,104)
    float u = g[64 + l];
    float v = (l < 8) ? g[96 + l] : -1e30f;
    float m2 = fmaxf(u, v);
#pragma unroll
    for (int o = 16; o; o >>= 1) m2 = fmaxf(m2, __shfl_xor_sync(0xffffffffu, m2, o));
    float e1 = expf(u - m2);
    float e2 = (l < 8) ? expf(v - m2) : 0.f;
    float s2 = e1 + e2;
#pragma unroll
    for (int o = 16; o; o >>= 1) s2 += __shfl_xor_sync(0xffffffffu, s2, o);
    float inv = 1.f / s2;
    out_sim[wg * 40 + l] = e1 * inv;
    if (l < 8) out_sim[wg * 40 + 32 + l] = e2 * inv;

    // ---- sigmoids
    if (l == 0) out_hom[wg] = 1.f / (1.f + expf(-g[104]));
    if (l == 1) out_ent[wg] = 1.f / (1.f + expf(-g[105]));
}

// ---------------- launch ------------------------------------------------------
extern "C" void kernel_launch(void* const* d_in, const int* in_sizes, int n_in,
                              void* d_out, int out_size) {
    const float* x     = (const float*)d_in[0];
    const void*  eidx  = d_in[1];
    const float* w1    = (const float*)d_in[2];
    const float* b1    = (const float*)d_in[3];
    const float* w2    = (const float*)d_in[4];
    const float* b2    = (const float*)d_in[5];
    const float* gamma = (const float*)d_in[6];
    const float* beta  = (const float*)d_in[7];
    const float* mean  = (const float*)d_in[8];
    const float* var   = (const float*)d_in[9];
    const float* cls_w = (const float*)d_in[10];
    const float* cls_b = (const float*)d_in[11];
    const float* sim_w = (const float*)d_in[12];
    const float* sim_b = (const float*)d_in[13];
    const float* hom_w = (const float*)d_in[14];
    const float* hom_b = (const float*)d_in[15];
    const float* ent_w = (const float*)d_in[16];
    const float* ent_b = (const float*)d_in[17];

    int N = in_sizes[0] / F;
    long long E = (long long)in_sizes[1] / 2;
    float* out = (float*)d_out;

    float *p_h = nullptr, *p_agg = nullptr, *p_head = nullptr, *p_hw = nullptr,
          *p_hb = nullptr;
    cudaGetSymbolAddress((void**)&p_h, g_h);
    cudaGetSymbolAddress((void**)&p_agg, g_agg);
    cudaGetSymbolAddress((void**)&p_head, g_head);
    cudaGetSymbolAddress((void**)&p_hw, g_hw);
    cudaGetSymbolAddress((void**)&p_hb, g_hb);

    // opt-in to >48KB dynamic smem for the GEMM
    cudaFuncSetAttribute(gemm_kernel, cudaFuncAttributeMaxDynamicSharedMemorySize,
                         96 * 1024);
    size_t smem128 = (size_t)(F * 128 + 8 * 4 * F + 128) * sizeof(float);
    size_t smem106 = (size_t)(F * 108 + 8 * 4 * F + 108) * sizeof(float);

    int tb = 256;
    long long nt;

    // 0) dtype detection
    detect_kernel<<<1, 32>>>((const int*)eidx);

    // 1) degrees -> dinv
    zero_deg_kernel<<<(N + tb - 1) / tb, tb>>>(N);
    count_deg_kernel<<<(unsigned)((E + tb - 1) / tb), tb>>>(eidx, E);
    dinv_kernel<<<(N + tb - 1) / tb, tb>>>(N);

    // 2) layer 1: h = x @ w1 ; aggregate ; BN+ReLU
    gemm_kernel<<<(N + 31) / 32, tb, smem128>>>(x, w1, nullptr, p_h, N, F);
    nt = (long long)N * 32;
    init_agg_kernel<<<(unsigned)((nt + tb - 1) / tb), tb>>>(N);
    scatter_kernel<<<(unsigned)((E + 7) / 8), tb>>>(eidx, E);
    nt = (long long)N * F;
    epi1_kernel<<<(unsigned)((nt + tb - 1) / tb), tb>>>(N, b1, gamma, beta, mean, var);

    // 3) layer 2: h = relu_h @ w2 ; aggregate ; +b2
    gemm_kernel<<<(N + 31) / 32, tb, smem128>>>(p_agg, w2, nullptr, p_h, N, F);
    nt = (long long)N * 32;
    init_agg_kernel<<<(unsigned)((nt + tb - 1) / tb), tb>>>(N);
    scatter_kernel<<<(unsigned)((E + 7) / 8), tb>>>(eidx, E);
    nt = (long long)N * F;
    epi2_kernel<<<(unsigned)((nt + tb - 1) / tb), tb>>>(N, b2);

    // 4) heads: pack weights, fused GEMM [N,106], then softmax/sigmoid finisher
    pack_heads_kernel<<<(F * HEADC + tb - 1) / tb, tb>>>(cls_w, cls_b, sim_w, sim_b,
                                                         hom_w, hom_b, ent_w, ent_b);
    gemm_kernel<<<(N + 31) / 32, tb, smem106>>>(p_agg, p_hw, p_hb, p_head, N, HEADC);
    finish_kernel<<<(N + 7) / 8, tb>>>(N, out);
}

// round 2
// speedup vs baseline: 1.5895x; 1.5895x over previous
#include <cuda_runtime.h>
#include <math.h>
#include <stdint.h>

#define NMAX 100000
#define EMAX 1600000
#define F 128
#define HEADC 106   // 64 + 40 + 1 + 1
#define HEADP 108

// ---------------- scratch (static device globals; no allocation allowed) ---
__device__ float g_h[(size_t)NMAX * F];       // GEMM output / gather source
__device__ float g_agg[(size_t)NMAX * F];     // aggregation output
__device__ float g_dinv[NMAX];
__device__ int   g_deg[NMAX];
__device__ int   g_rowptr[NMAX + 1];
__device__ int   g_fill[NMAX];
__device__ int   g_row[EMAX];
__device__ int   g_col[EMAX];
__device__ int   g_src[EMAX];                 // CSR (by destination) source ids
__device__ float g_hw[F * HEADP];
__device__ float g_hb[HEADP];
__device__ int   g_is64;

// ---------------- dtype detection: int64 vs int32 edge_index ---------------
__global__ void detect_kernel(const int* __restrict__ e) {
    int l = threadIdx.x;
    int bad = 0;
    for (int j = l; j < 256; j += 32)
        if (e[2 * j + 1] != 0) bad = 1;
    unsigned b = __ballot_sync(0xffffffffu, bad);
    if (l == 0) g_is64 = (b == 0) ? 1 : 0;
}

__device__ __forceinline__ int ldidx(const void* p, long long i, int is64) {
    return is64 ? (int)((const long long*)p)[i] : ((const int*)p)[i];
}

// ---------------- convert indices to int32 + zero degree --------------------
__global__ void convert_kernel(const void* __restrict__ eidx, long long E, int n) {
    long long t = (long long)blockIdx.x * blockDim.x + threadIdx.x;
    int is64 = g_is64;
    if (t < E) {
        g_row[t] = ldidx(eidx, t, is64);
        g_col[t] = ldidx(eidx, E + t, is64);
    }
    if (t < n) g_deg[t] = 0;
}

__global__ void count_deg_kernel(long long E) {
    long long e = (long long)blockIdx.x * blockDim.x + threadIdx.x;
    if (e >= E) return;
    atomicAdd(&g_deg[g_col[e]], 1);
}

// ---------------- single-block scan: rowptr, fill cursors, dinv -------------
__global__ void scan_kernel(int n) {
    __shared__ int ssum[1024];
    int t = threadIdx.x;
    int chunk = (n + 1023) >> 10;
    int lo = t * chunk;
    int hi = lo + chunk; if (hi > n) hi = n;

    int s = 0;
    for (int i = lo; i < hi; i++) s += g_deg[i];
    ssum[t] = s;
    __syncthreads();
    for (int off = 1; off < 1024; off <<= 1) {
        int v = (t >= off) ? ssum[t - off] : 0;
        __syncthreads();
        ssum[t] += v;
        __syncthreads();
    }
    int run = ssum[t] - s;  // exclusive prefix
    for (int i = lo; i < hi; i++) {
        int d = g_deg[i];
        g_rowptr[i] = run;
        g_fill[i]   = run;
        g_dinv[i]   = rsqrtf((float)(d + 1));  // +1 self-loop
        run += d;
    }
    if (t == 1023) g_rowptr[n] = ssum[1023];
}

__global__ void fill_kernel(long long E) {
    long long e = (long long)blockIdx.x * blockDim.x + threadIdx.x;
    if (e >= E) return;
    int c = g_col[e];
    int pos = atomicAdd(&g_fill[c], 1);
    g_src[pos] = g_row[e];
}

// ---------------- generic SGEMM: C[M,128] = A[M,128] @ W[128,128] -----------
__global__ void gemm_kernel(const float* __restrict__ A,
                            const float* __restrict__ W,
                            float* __restrict__ C, int M) {
    extern __shared__ float sm[];
    float* Ws = sm;                    // F * F
    float* xs = Ws + F * F;            // 8 warps * 4 rows * F

    int tid = threadIdx.x;
    for (int i = tid; i < F * F; i += blockDim.x) Ws[i] = W[i];
    __syncthreads();

    int wid = tid >> 5, l = tid & 31;
    long long row0 = ((long long)blockIdx.x * 8 + wid) * 4;
    if (row0 >= M) return;

    float* xw = xs + wid * 4 * F;
#pragma unroll
    for (int rr = 0; rr < 4; rr++) {
        long long r = row0 + rr;
        float4 v = make_float4(0.f, 0.f, 0.f, 0.f);
        if (r < M) v = __ldg((const float4*)(A + r * F) + l);
        *(float4*)&xw[rr * F + 4 * l] = v;
    }
    __syncwarp();

    float acc[4][4];
#pragma unroll
    for (int rr = 0; rr < 4; rr++)
#pragma unroll
        for (int m = 0; m < 4; m++) acc[rr][m] = 0.f;

    const float4* WsV = (const float4*)Ws;
#pragma unroll
    for (int k = 0; k < F; k += 4) {
        float4 w4[4], xr[4];
#pragma unroll
        for (int kk = 0; kk < 4; kk++) w4[kk] = WsV[(k + kk) * 32 + l];
#pragma unroll
        for (int rr = 0; rr < 4; rr++) xr[rr] = *(const float4*)&xw[rr * F + k];
#pragma unroll
        for (int rr = 0; rr < 4; rr++) {
            const float* xf = (const float*)&xr[rr];
#pragma unroll
            for (int kk = 0; kk < 4; kk++) {
                const float* wf = (const float*)&w4[kk];
                float xv = xf[kk];
                acc[rr][0] += xv * wf[0];
                acc[rr][1] += xv * wf[1];
                acc[rr][2] += xv * wf[2];
                acc[rr][3] += xv * wf[3];
            }
        }
    }

#pragma unroll
    for (int rr = 0; rr < 4; rr++) {
        long long r = row0 + rr;
        if (r >= M) break;
        *(float4*)(C + r * F + 4 * l) =
            make_float4(acc[rr][0], acc[rr][1], acc[rr][2], acc[rr][3]);
    }
}

// ---------------- CSR gather aggregation (no atomics), fused epilogue ------
// mode 1: +b1, BN(eval), ReLU.   mode 2: +b2.
__global__ void agg_kernel(int n, int mode,
                           const float* __restrict__ bias,
                           const float* __restrict__ gamma,
                           const float* __restrict__ beta,
                           const float* __restrict__ mean,
                           const float* __restrict__ var) {
    int node = blockIdx.x * (blockDim.x >> 5) + (threadIdx.x >> 5);
    if (node >= n) return;
    int l = threadIdx.x & 31;

    float d = g_dinv[node];
    const float4* hv = (const float4*)g_h;

    // self-loop term
    float4 acc = hv[(size_t)node * 32 + l];
    float d2 = d * d;
    acc.x *= d2; acc.y *= d2; acc.z *= d2; acc.w *= d2;
    float4 acc2 = make_float4(0.f, 0.f, 0.f, 0.f);

    int s = g_rowptr[node], e2 = g_rowptr[node + 1];
    for (int base = s; base < e2; base += 32) {
        int idx = base + l;
        int r = (idx < e2) ? g_src[idx] : 0;
        float dr = (idx < e2) ? g_dinv[r] : 0.f;
        int m = e2 - base; if (m > 32) m = 32;
        int j = 0;
        for (; j + 2 <= m; j += 2) {
            int r0 = __shfl_sync(0xffffffffu, r, j);
            int r1 = __shfl_sync(0xffffffffu, r, j + 1);
            float n0 = __shfl_sync(0xffffffffu, dr, j) * d;
            float n1 = __shfl_sync(0xffffffffu, dr, j + 1) * d;
            float4 v0 = __ldg(hv + (size_t)r0 * 32 + l);
            float4 v1 = __ldg(hv + (size_t)r1 * 32 + l);
            acc.x += v0.x * n0; acc.y += v0.y * n0;
            acc.z += v0.z * n0; acc.w += v0.w * n0;
            acc2.x += v1.x * n1; acc2.y += v1.y * n1;
            acc2.z += v1.z * n1; acc2.w += v1.w * n1;
        }
        if (j < m) {
            int r0 = __shfl_sync(0xffffffffu, r, j);
            float n0 = __shfl_sync(0xffffffffu, dr, j) * d;
            float4 v0 = __ldg(hv + (size_t)r0 * 32 + l);
            acc.x += v0.x * n0; acc.y += v0.y * n0;
            acc.z += v0.z * n0; acc.w += v0.w * n0;
        }
    }
    acc.x += acc2.x; acc.y += acc2.y; acc.z += acc2.z; acc.w += acc2.w;

    int c0 = 4 * l;
    float out[4] = {acc.x, acc.y, acc.z, acc.w};
    if (mode == 1) {
#pragma unroll
        for (int m = 0; m < 4; m++) {
            int c = c0 + m;
            float v = out[m] + bias[c];
            float sc = gamma[c] * rsqrtf(var[c] + 1e-5f);
            v = (v - mean[c]) * sc + beta[c];
            out[m] = fmaxf(v, 0.f);
        }
    } else {
#pragma unroll
        for (int m = 0; m < 4; m++) out[m] += bias[c0 + m];
    }
    *(float4*)(g_agg + (size_t)node * F + c0) =
        make_float4(out[0], out[1], out[2], out[3]);
}

// ---------------- head weight packing ---------------------------------------
__global__ void pack_heads_kernel(const float* __restrict__ cls_w,
                                  const float* __restrict__ cls_b,
                                  const float* __restrict__ sim_w,
                                  const float* __restrict__ sim_b,
                                  const float* __restrict__ hom_w,
                                  const float* __restrict__ hom_b,
                                  const float* __restrict__ ent_w,
                                  const float* __restrict__ ent_b) {
    int t = blockIdx.x * blockDim.x + threadIdx.x;
    if (t < F * HEADP) {
        int k = t / HEADP, c = t % HEADP;
        float v = 0.f;
        if (c < 64)        v = cls_w[k * 64 + c];
        else if (c < 104)  v = sim_w[k * 40 + (c - 64)];
        else if (c == 104) v = hom_w[k];
        else if (c == 105) v = ent_w[k];
        g_hw[t] = v;
    }
    if (t < HEADP) {
        float v = 0.f;
        if (t < 64)        v = cls_b[t];
        else if (t < 104)  v = sim_b[t - 64];
        else if (t == 104) v = hom_b[0];
        else if (t == 105) v = ent_b[0];
        g_hb[t] = v;
    }
}

// ---------------- head GEMM [M,128]x[128,106] with fused finisher -----------
__global__ void head_kernel(const float* __restrict__ A,
                            float* __restrict__ out, int M) {
    extern __shared__ float sm[];
    float* Ws = sm;                    // F * HEADP
    float* xs = Ws + F * HEADP;        // 8 * 4 * F
    float* sb = xs + 8 * 4 * F;        // HEADP

    int tid = threadIdx.x;
    for (int i = tid; i < F * HEADP; i += blockDim.x) Ws[i] = g_hw[i];
    for (int c = tid; c < HEADP; c += blockDim.x) sb[c] = g_hb[c];
    __syncthreads();

    int wid = tid >> 5, l = tid & 31;
    long long row0 = ((long long)blockIdx.x * 8 + wid) * 4;
    if (row0 >= M) return;

    float* xw = xs + wid * 4 * F;
#pragma unroll
    for (int rr = 0; rr < 4; rr++) {
        long long r = row0 + rr;
        float4 v = make_float4(0.f, 0.f, 0.f, 0.f);
        if (r < M) v = __ldg((const float4*)(A + r * F) + l);
        *(float4*)&xw[rr * F + 4 * l] = v;
    }
    __syncwarp();

    float acc[4][4];
#pragma unroll
    for (int rr = 0; rr < 4; rr++)
#pragma unroll
        for (int m = 0; m < 4; m++) acc[rr][m] = 0.f;

    const float4* WsV = (const float4*)Ws;
    const int ncp4 = HEADP >> 2;  // 27
#pragma unroll
    for (int k = 0; k < F; k += 4) {
        float4 w4[4], xr[4];
#pragma unroll
        for (int kk = 0; kk < 4; kk++)
            w4[kk] = (l < ncp4) ? WsV[(k + kk) * ncp4 + l]
                                : make_float4(0.f, 0.f, 0.f, 0.f);
#pragma unroll
        for (int rr = 0; rr < 4; rr++) xr[rr] = *(const float4*)&xw[rr * F + k];
#pragma unroll
        for (int rr = 0; rr < 4; rr++) {
            const float* xf = (const float*)&xr[rr];
#pragma unroll
            for (int kk = 0; kk < 4; kk++) {
                const float* wf = (const float*)&w4[kk];
                float xv = xf[kk];
                acc[rr][0] += xv * wf[0];
                acc[rr][1] += xv * wf[1];
                acc[rr][2] += xv * wf[2];
                acc[rr][3] += xv * wf[3];
            }
        }
    }

    float* out_main = out;                     // [M,64]
    float* out_sim  = out + (size_t)M * 64;    // [M,40]
    float* out_hom  = out + (size_t)M * 104;   // [M]
    float* out_ent  = out + (size_t)M * 105;   // [M]

    int c0 = 4 * l;
#pragma unroll
    for (int rr = 0; rr < 4; rr++) {
        long long r = row0 + rr;
        if (r >= M) break;
        float v[4];
#pragma unroll
        for (int m = 0; m < 4; m++)
            v[m] = acc[rr][m] + ((l < ncp4) ? sb[c0 + m] : 0.f);

        // log_softmax over cols [0,64) -> lanes 0..15
        float lm = -3.0e38f;
        if (l < 16) {
#pragma unroll
            for (int m = 0; m < 4; m++) lm = fmaxf(lm, v[m]);
        }
#pragma unroll
        for (int o = 16; o; o >>= 1)
            lm = fmaxf(lm, __shfl_xor_sync(0xffffffffu, lm, o));
        float se = 0.f;
        if (l < 16) {
#pragma unroll
            for (int m = 0; m < 4; m++) se += expf(v[m] - lm);
        }
#pragma unroll
        for (int o = 16; o; o >>= 1) se += __shfl_xor_sync(0xffffffffu, se, o);
        float ls = lm + logf(se);
        if (l < 16) {
#pragma unroll
            for (int m = 0; m < 4; m++) out_main[r * 64 + c0 + m] = v[m] - ls;
        }

        // softmax over cols [64,104) -> lanes 16..25
        bool insim = (l >= 16 && l < 26);
        float lm2 = -3.0e38f;
        if (insim) {
#pragma unroll
            for (int m = 0; m < 4; m++) lm2 = fmaxf(lm2, v[m]);
        }
#pragma unroll
        for (int o = 16; o; o >>= 1)
            lm2 = fmaxf(lm2, __shfl_xor_sync(0xffffffffu, lm2, o));
        float e4[4];
        float se2 = 0.f;
        if (insim) {
#pragma unroll
            for (int m = 0; m < 4; m++) { e4[m] = expf(v[m] - lm2); se2 += e4[m]; }
        }
#pragma unroll
        for (int o = 16; o; o >>= 1) se2 += __shfl_xor_sync(0xffffffffu, se2, o);
        if (insim) {
            float inv = 1.f / se2;
#pragma unroll
            for (int m = 0; m < 4; m++)
                out_sim[r * 40 + (c0 - 64) + m] = e4[m] * inv;
        }

        // sigmoids: col 104, 105 -> lane 26
        if (l == 26) {
            out_hom[r] = 1.f / (1.f + expf(-v[0]));
            out_ent[r] = 1.f / (1.f + expf(-v[1]));
        }
    }
}

// ---------------- launch ------------------------------------------------------
extern "C" void kernel_launch(void* const* d_in, const int* in_sizes, int n_in,
                              void* d_out, int out_size) {
    const float* x     = (const float*)d_in[0];
    const void*  eidx  = d_in[1];
    const float* w1    = (const float*)d_in[2];
    const float* b1    = (const float*)d_in[3];
    const float* w2    = (const float*)d_in[4];
    const float* b2    = (const float*)d_in[5];
    const float* gamma = (const float*)d_in[6];
    const float* beta  = (const float*)d_in[7];
    const float* mean  = (const float*)d_in[8];
    const float* var   = (const float*)d_in[9];
    const float* cls_w = (const float*)d_in[10];
    const float* cls_b = (const float*)d_in[11];
    const float* sim_w = (const float*)d_in[12];
    const float* sim_b = (const float*)d_in[13];
    const float* hom_w = (const float*)d_in[14];
    const float* hom_b = (const float*)d_in[15];
    const float* ent_w = (const float*)d_in[16];
    const float* ent_b = (const float*)d_in[17];

    int N = in_sizes[0] / F;
    long long E = (long long)in_sizes[1] / 2;
    float* out = (float*)d_out;

    float *p_h = nullptr, *p_agg = nullptr;
    cudaGetSymbolAddress((void**)&p_h, g_h);
    cudaGetSymbolAddress((void**)&p_agg, g_agg);

    cudaFuncSetAttribute(gemm_kernel, cudaFuncAttributeMaxDynamicSharedMemorySize,
                         96 * 1024);
    cudaFuncSetAttribute(head_kernel, cudaFuncAttributeMaxDynamicSharedMemorySize,
                         96 * 1024);
    size_t smemG = (size_t)(F * F + 8 * 4 * F) * sizeof(float);
    size_t smemH = (size_t)(F * HEADP + 8 * 4 * F + HEADP) * sizeof(float);

    int tb = 256;

    // 0) detect dtype, 1) convert + zero deg, 2) count, 3) scan, 4) fill
    detect_kernel<<<1, 32>>>((const int*)eidx);
    long long mx = (E > N) ? E : N;
    convert_kernel<<<(unsigned)((mx + tb - 1) / tb), tb>>>(eidx, E, N);
    count_deg_kernel<<<(unsigned)((E + tb - 1) / tb), tb>>>(E);
    scan_kernel<<<1, 1024>>>(N);
    fill_kernel<<<(unsigned)((E + tb - 1) / tb), tb>>>(E);

    // layer 1
    gemm_kernel<<<(N + 31) / 32, tb, smemG>>>(x, w1, p_h, N);
    agg_kernel<<<(N + 7) / 8, tb>>>(N, 1, b1, gamma, beta, mean, var);

    // layer 2
    gemm_kernel<<<(N + 31) / 32, tb, smemG>>>(p_agg, w2, p_h, N);
    agg_kernel<<<(N + 7) / 8, tb>>>(N, 2, b2, nullptr, nullptr, nullptr, nullptr);

    // heads (fused finisher)
    pack_heads_kernel<<<(F * HEADP + tb - 1) / tb, tb>>>(cls_w, cls_b, sim_w, sim_b,
                                                         hom_w, hom_b, ent_w, ent_b);
    head_kernel<<<(N + 31) / 32, tb, smemH>>>(p_agg, out, N);
}

// round 3
// speedup vs baseline: 2.1754x; 1.3686x over previous
#include <cuda_runtime.h>
#include <math.h>
#include <stdint.h>

#define NMAX 100000
#define EMAX 1600000
#define F 128
#define HEADC 106   // 64 + 40 + 1 + 1
#define HEADP 108
#define SCHUNK 512

// ---------------- scratch (static device globals; no allocation allowed) ---
__device__ float g_h[(size_t)NMAX * F];       // GEMM output / gather source
__device__ float g_agg[(size_t)NMAX * F];     // aggregation output
__device__ float g_dinv[NMAX];
__device__ int   g_deg[NMAX];
__device__ int   g_rowptr[NMAX + 1];
__device__ int   g_fill[NMAX];
__device__ int   g_row[EMAX];
__device__ int   g_col[EMAX];
__device__ int   g_src[EMAX];                 // CSR (by destination) source ids
__device__ int   g_bsum[256];
__device__ float g_hw[F * HEADP];
__device__ float g_hb[HEADP];
__device__ int   g_is64;

// ---------------- dtype detection: int64 vs int32 edge_index ---------------
__global__ void detect_kernel(const int* __restrict__ e) {
    int l = threadIdx.x;
    int bad = 0;
    for (int j = l; j < 256; j += 32)
        if (e[2 * j + 1] != 0) bad = 1;
    unsigned b = __ballot_sync(0xffffffffu, bad);
    if (l == 0) g_is64 = (b == 0) ? 1 : 0;
}

__device__ __forceinline__ int ldidx(const void* p, long long i, int is64) {
    return is64 ? (int)((const long long*)p)[i] : ((const int*)p)[i];
}

// ---------------- convert indices to int32 + zero degree --------------------
__global__ void convert_kernel(const void* __restrict__ eidx, long long E, int n) {
    long long t = (long long)blockIdx.x * blockDim.x + threadIdx.x;
    int is64 = g_is64;
    if (t < E) {
        g_row[t] = ldidx(eidx, t, is64);
        g_col[t] = ldidx(eidx, E + t, is64);
    }
    if (t < n) g_deg[t] = 0;
}

__global__ void count_deg_kernel(long long E) {
    long long e = (long long)blockIdx.x * blockDim.x + threadIdx.x;
    if (e >= E) return;
    atomicAdd(&g_deg[g_col[e]], 1);
}

// ---------------- hierarchical scan (3 stages, all parallel) ----------------
__global__ void scan1_kernel(int n) {
    __shared__ int sh[SCHUNK];
    int t = threadIdx.x;
    int i = blockIdx.x * SCHUNK + t;
    sh[t] = (i < n) ? g_deg[i] : 0;
    __syncthreads();
#pragma unroll
    for (int off = SCHUNK / 2; off; off >>= 1) {
        if (t < off) sh[t] += sh[t + off];
        __syncthreads();
    }
    if (t == 0) g_bsum[blockIdx.x] = sh[0];
}

__global__ void scan2_kernel(int nb, int n) {
    __shared__ int sh[256];
    int t = threadIdx.x;
    int v = (t < nb) ? g_bsum[t] : 0;
    sh[t] = v;
    __syncthreads();
#pragma unroll
    for (int off = 1; off < 256; off <<= 1) {
        int u = (t >= off) ? sh[t - off] : 0;
        __syncthreads();
        sh[t] += u;
        __syncthreads();
    }
    if (t < nb) g_bsum[t] = sh[t] - v;   // exclusive
    if (t == 255) g_rowptr[n] = sh[255];
}

__global__ void scan3_kernel(int n) {
    __shared__ int sh[SCHUNK];
    int t = threadIdx.x;
    int i = blockIdx.x * SCHUNK + t;
    int d = (i < n) ? g_deg[i] : 0;
    sh[t] = d;
    __syncthreads();
#pragma unroll
    for (int off = 1; off < SCHUNK; off <<= 1) {
        int u = (t >= off) ? sh[t - off] : 0;
        __syncthreads();
        sh[t] += u;
        __syncthreads();
    }
    if (i < n) {
        int pre = g_bsum[blockIdx.x] + sh[t] - d;
        g_rowptr[i] = pre;
        g_fill[i]   = pre;
        g_dinv[i]   = rsqrtf((float)(d + 1));  // +1 self-loop
    }
}

__global__ void fill_kernel(long long E) {
    long long e = (long long)blockIdx.x * blockDim.x + threadIdx.x;
    if (e >= E) return;
    int c = g_col[e];
    int pos = atomicAdd(&g_fill[c], 1);
    g_src[pos] = g_row[e];
}

// ---------------- generic SGEMM: C[M,128] = A[M,128] @ W[128,128] -----------
__global__ void gemm_kernel(const float* __restrict__ A,
                            const float* __restrict__ W,
                            float* __restrict__ C, int M) {
    extern __shared__ float sm[];
    float* Ws = sm;                    // F * F
    float* xs = Ws + F * F;            // 8 warps * 4 rows * F

    int tid = threadIdx.x;
    for (int i = tid; i < F * F; i += blockDim.x) Ws[i] = W[i];
    __syncthreads();

    int wid = tid >> 5, l = tid & 31;
    long long row0 = ((long long)blockIdx.x * 8 + wid) * 4;
    if (row0 >= M) return;

    float* xw = xs + wid * 4 * F;
#pragma unroll
    for (int rr = 0; rr < 4; rr++) {
        long long r = row0 + rr;
        float4 v = make_float4(0.f, 0.f, 0.f, 0.f);
        if (r < M) v = __ldg((const float4*)(A + r * F) + l);
        *(float4*)&xw[rr * F + 4 * l] = v;
    }
    __syncwarp();

    float acc[4][4];
#pragma unroll
    for (int rr = 0; rr < 4; rr++)
#pragma unroll
        for (int m = 0; m < 4; m++) acc[rr][m] = 0.f;

    const float4* WsV = (const float4*)Ws;
#pragma unroll
    for (int k = 0; k < F; k += 4) {
        float4 w4[4], xr[4];
#pragma unroll
        for (int kk = 0; kk < 4; kk++) w4[kk] = WsV[(k + kk) * 32 + l];
#pragma unroll
        for (int rr = 0; rr < 4; rr++) xr[rr] = *(const float4*)&xw[rr * F + k];
#pragma unroll
        for (int rr = 0; rr < 4; rr++) {
            const float* xf = (const float*)&xr[rr];
#pragma unroll
            for (int kk = 0; kk < 4; kk++) {
                const float* wf = (const float*)&w4[kk];
                float xv = xf[kk];
                acc[rr][0] += xv * wf[0];
                acc[rr][1] += xv * wf[1];
                acc[rr][2] += xv * wf[2];
                acc[rr][3] += xv * wf[3];
            }
        }
    }

#pragma unroll
    for (int rr = 0; rr < 4; rr++) {
        long long r = row0 + rr;
        if (r >= M) break;
        *(float4*)(C + r * F + 4 * l) =
            make_float4(acc[rr][0], acc[rr][1], acc[rr][2], acc[rr][3]);
    }
}

// ---------------- CSR gather aggregation (no atomics), fused epilogue ------
// mode 1: +b1, BN(eval), ReLU.   mode 2: +b2.
__global__ void agg_kernel(int n, int mode,
                           const float* __restrict__ bias,
                           const float* __restrict__ gamma,
                           const float* __restrict__ beta,
                           const float* __restrict__ mean,
                           const float* __restrict__ var) {
    int node = blockIdx.x * (blockDim.x >> 5) + (threadIdx.x >> 5);
    if (node >= n) return;
    int l = threadIdx.x & 31;

    float d = g_dinv[node];
    const float4* hv = (const float4*)g_h;

    // self-loop term
    float4 acc = hv[(size_t)node * 32 + l];
    float d2 = d * d;
    acc.x *= d2; acc.y *= d2; acc.z *= d2; acc.w *= d2;
    float4 acc2 = make_float4(0.f, 0.f, 0.f, 0.f);

    int s = g_rowptr[node], e2 = g_rowptr[node + 1];
    for (int base = s; base < e2; base += 32) {
        int idx = base + l;
        int r = (idx < e2) ? g_src[idx] : 0;
        float dr = (idx < e2) ? g_dinv[r] : 0.f;
        int m = e2 - base; if (m > 32) m = 32;
        int j = 0;
        for (; j + 2 <= m; j += 2) {
            int r0 = __shfl_sync(0xffffffffu, r, j);
            int r1 = __shfl_sync(0xffffffffu, r, j + 1);
            float n0 = __shfl_sync(0xffffffffu, dr, j) * d;
            float n1 = __shfl_sync(0xffffffffu, dr, j + 1) * d;
            float4 v0 = __ldg(hv + (size_t)r0 * 32 + l);
            float4 v1 = __ldg(hv + (size_t)r1 * 32 + l);
            acc.x += v0.x * n0; acc.y += v0.y * n0;
            acc.z += v0.z * n0; acc.w += v0.w * n0;
            acc2.x += v1.x * n1; acc2.y += v1.y * n1;
            acc2.z += v1.z * n1; acc2.w += v1.w * n1;
        }
        if (j < m) {
            int r0 = __shfl_sync(0xffffffffu, r, j);
            float n0 = __shfl_sync(0xffffffffu, dr, j) * d;
            float4 v0 = __ldg(hv + (size_t)r0 * 32 + l);
            acc.x += v0.x * n0; acc.y += v0.y * n0;
            acc.z += v0.z * n0; acc.w += v0.w * n0;
        }
    }
    acc.x += acc2.x; acc.y += acc2.y; acc.z += acc2.z; acc.w += acc2.w;

    int c0 = 4 * l;
    float out[4] = {acc.x, acc.y, acc.z, acc.w};
    if (mode == 1) {
#pragma unroll
        for (int m = 0; m < 4; m++) {
            int c = c0 + m;
            float v = out[m] + bias[c];
            float sc = gamma[c] * rsqrtf(var[c] + 1e-5f);
            v = (v - mean[c]) * sc + beta[c];
            out[m] = fmaxf(v, 0.f);
        }
    } else {
#pragma unroll
        for (int m = 0; m < 4; m++) out[m] += bias[c0 + m];
    }
    *(float4*)(g_agg + (size_t)node * F + c0) =
        make_float4(out[0], out[1], out[2], out[3]);
}

// ---------------- head weight packing ---------------------------------------
__global__ void pack_heads_kernel(const float* __restrict__ cls_w,
                                  const float* __restrict__ cls_b,
                                  const float* __restrict__ sim_w,
                                  const float* __restrict__ sim_b,
                                  const float* __restrict__ hom_w,
                                  const float* __restrict__ hom_b,
                                  const float* __restrict__ ent_w,
                                  const float* __restrict__ ent_b) {
    int t = blockIdx.x * blockDim.x + threadIdx.x;
    if (t < F * HEADP) {
        int k = t / HEADP, c = t % HEADP;
        float v = 0.f;
        if (c < 64)        v = cls_w[k * 64 + c];
        else if (c < 104)  v = sim_w[k * 40 + (c - 64)];
        else if (c == 104) v = hom_w[k];
        else if (c == 105) v = ent_w[k];
        g_hw[t] = v;
    }
    if (t < HEADP) {
        float v = 0.f;
        if (t < 64)        v = cls_b[t];
        else if (t < 104)  v = sim_b[t - 64];
        else if (t == 104) v = hom_b[0];
        else if (t == 105) v = ent_b[0];
        g_hb[t] = v;
    }
}

// ---------------- head GEMM [M,128]x[128,106] with fused finisher -----------
__global__ void head_kernel(const float* __restrict__ A,
                            float* __restrict__ out, int M) {
    extern __shared__ float sm[];
    float* Ws = sm;                    // F * HEADP
    float* xs = Ws + F * HEADP;        // 8 * 4 * F
    float* sb = xs + 8 * 4 * F;        // HEADP

    int tid = threadIdx.x;
    for (int i = tid; i < F * HEADP; i += blockDim.x) Ws[i] = g_hw[i];
    for (int c = tid; c < HEADP; c += blockDim.x) sb[c] = g_hb[c];
    __syncthreads();

    int wid = tid >> 5, l = tid & 31;
    long long row0 = ((long long)blockIdx.x * 8 + wid) * 4;
    if (row0 >= M) return;

    float* xw = xs + wid * 4 * F;
#pragma unroll
    for (int rr = 0; rr < 4; rr++) {
        long long r = row0 + rr;
        float4 v = make_float4(0.f, 0.f, 0.f, 0.f);
        if (r < M) v = __ldg((const float4*)(A + r * F) + l);
        *(float4*)&xw[rr * F + 4 * l] = v;
    }
    __syncwarp();

    float acc[4][4];
#pragma unroll
    for (int rr = 0; rr < 4; rr++)
#pragma unroll
        for (int m = 0; m < 4; m++) acc[rr][m] = 0.f;

    const float4* WsV = (const float4*)Ws;
    const int ncp4 = HEADP >> 2;  // 27
#pragma unroll
    for (int k = 0; k < F; k += 4) {
        float4 w4[4], xr[4];
#pragma unroll
        for (int kk = 0; kk < 4; kk++)
            w4[kk] = (l < ncp4) ? WsV[(k + kk) * ncp4 + l]
                                : make_float4(0.f, 0.f, 0.f, 0.f);
#pragma unroll
        for (int rr = 0; rr < 4; rr++) xr[rr] = *(const float4*)&xw[rr * F + k];
#pragma unroll
        for (int rr = 0; rr < 4; rr++) {
            const float* xf = (const float*)&xr[rr];
#pragma unroll
            for (int kk = 0; kk < 4; kk++) {
                const float* wf = (const float*)&w4[kk];
                float xv = xf[kk];
                acc[rr][0] += xv * wf[0];
                acc[rr][1] += xv * wf[1];
                acc[rr][2] += xv * wf[2];
                acc[rr][3] += xv * wf[3];
            }
        }
    }

    float* out_main = out;                     // [M,64]
    float* out_sim  = out + (size_t)M * 64;    // [M,40]
    float* out_hom  = out + (size_t)M * 104;   // [M]
    float* out_ent  = out + (size_t)M * 105;   // [M]

    int c0 = 4 * l;
#pragma unroll
    for (int rr = 0; rr < 4; rr++) {
        long long r = row0 + rr;
        if (r >= M) break;
        float v[4];
#pragma unroll
        for (int m = 0; m < 4; m++)
            v[m] = acc[rr][m] + ((l < ncp4) ? sb[c0 + m] : 0.f);

        // log_softmax over cols [0,64) -> lanes 0..15
        float lm = -3.0e38f;
        if (l < 16) {
#pragma unroll
            for (int m = 0; m < 4; m++) lm = fmaxf(lm, v[m]);
        }
#pragma unroll
        for (int o = 16; o; o >>= 1)
            lm = fmaxf(lm, __shfl_xor_sync(0xffffffffu, lm, o));
        float se = 0.f;
        if (l < 16) {
#pragma unroll
            for (int m = 0; m < 4; m++) se += expf(v[m] - lm);
        }
#pragma unroll
        for (int o = 16; o; o >>= 1) se += __shfl_xor_sync(0xffffffffu, se, o);
        float ls = lm + logf(se);
        if (l < 16) {
#pragma unroll
            for (int m = 0; m < 4; m++) out_main[r * 64 + c0 + m] = v[m] - ls;
        }

        // softmax over cols [64,104) -> lanes 16..25
        bool insim = (l >= 16 && l < 26);
        float lm2 = -3.0e38f;
        if (insim) {
#pragma unroll
            for (int m = 0; m < 4; m++) lm2 = fmaxf(lm2, v[m]);
        }
#pragma unroll
        for (int o = 16; o; o >>= 1)
            lm2 = fmaxf(lm2, __shfl_xor_sync(0xffffffffu, lm2, o));
        float e4[4];
        float se2 = 0.f;
        if (insim) {
#pragma unroll
            for (int m = 0; m < 4; m++) { e4[m] = expf(v[m] - lm2); se2 += e4[m]; }
        }
#pragma unroll
        for (int o = 16; o; o >>= 1) se2 += __shfl_xor_sync(0xffffffffu, se2, o);
        if (insim) {
            float inv = 1.f / se2;
#pragma unroll
            for (int m = 0; m < 4; m++)
                out_sim[r * 40 + (c0 - 64) + m] = e4[m] * inv;
        }

        // sigmoids: col 104, 105 -> lane 26
        if (l == 26) {
            out_hom[r] = 1.f / (1.f + expf(-v[0]));
            out_ent[r] = 1.f / (1.f + expf(-v[1]));
        }
    }
}

// ---------------- launch ------------------------------------------------------
extern "C" void kernel_launch(void* const* d_in, const int* in_sizes, int n_in,
                              void* d_out, int out_size) {
    const float* x     = (const float*)d_in[0];
    const void*  eidx  = d_in[1];
    const float* w1    = (const float*)d_in[2];
    const float* b1    = (const float*)d_in[3];
    const float* w2    = (const float*)d_in[4];
    const float* b2    = (const float*)d_in[5];
    const float* gamma = (const float*)d_in[6];
    const float* beta  = (const float*)d_in[7];
    const float* mean  = (const float*)d_in[8];
    const float* var   = (const float*)d_in[9];
    const float* cls_w = (const float*)d_in[10];
    const float* cls_b = (const float*)d_in[11];
    const float* sim_w = (const float*)d_in[12];
    const float* sim_b = (const float*)d_in[13];
    const float* hom_w = (const float*)d_in[14];
    const float* hom_b = (const float*)d_in[15];
    const float* ent_w = (const float*)d_in[16];
    const float* ent_b = (const float*)d_in[17];

    int N = in_sizes[0] / F;
    long long E = (long long)in_sizes[1] / 2;
    float* out = (float*)d_out;

    float *p_h = nullptr, *p_agg = nullptr;
    cudaGetSymbolAddress((void**)&p_h, g_h);
    cudaGetSymbolAddress((void**)&p_agg, g_agg);

    cudaFuncSetAttribute(gemm_kernel, cudaFuncAttributeMaxDynamicSharedMemorySize,
                         96 * 1024);
    cudaFuncSetAttribute(head_kernel, cudaFuncAttributeMaxDynamicSharedMemorySize,
                         96 * 1024);
    size_t smemG = (size_t)(F * F + 8 * 4 * F) * sizeof(float);
    size_t smemH = (size_t)(F * HEADP + 8 * 4 * F + HEADP) * sizeof(float);

    int tb = 256;
    int nscan = (N + SCHUNK - 1) / SCHUNK;

    // 0) detect dtype, 1) convert + zero deg, 2) count, 3) scan x3, 4) fill
    detect_kernel<<<1, 32>>>((const int*)eidx);
    long long mx = (E > N) ? E : N;
    convert_kernel<<<(unsigned)((mx + tb - 1) / tb), tb>>>(eidx, E, N);
    count_deg_kernel<<<(unsigned)((E + tb - 1) / tb), tb>>>(E);
    scan1_kernel<<<nscan, SCHUNK>>>(N);
    scan2_kernel<<<1, 256>>>(nscan, N);
    scan3_kernel<<<nscan, SCHUNK>>>(N);
    fill_kernel<<<(unsigned)((E + tb - 1) / tb), tb>>>(E);

    // layer 1
    gemm_kernel<<<(N + 31) / 32, tb, smemG>>>(x, w1, p_h, N);
    agg_kernel<<<(N + 7) / 8, tb>>>(N, 1, b1, gamma, beta, mean, var);

    // layer 2
    gemm_kernel<<<(N + 31) / 32, tb, smemG>>>(p_agg, w2, p_h, N);
    agg_kernel<<<(N + 7) / 8, tb>>>(N, 2, b2, nullptr, nullptr, nullptr, nullptr);

    // heads (fused finisher)
    pack_heads_kernel<<<(F * HEADP + tb - 1) / tb, tb>>>(cls_w, cls_b, sim_w, sim_b,
                                                         hom_w, hom_b, ent_w, ent_b);
    head_kernel<<<(N + 31) / 32, tb, smemH>>>(p_agg, out, N);
}